// round 1
// baseline (speedup 1.0000x reference)
#include <cuda_runtime.h>
#include <cstdint>

#define BATCH 16
#define D 512
#define LDIM 513
#define NITER 128   // 64 reference iterations x 2 half-steps

// Scratch (static device arrays; no allocation)
__device__ float g_K[(size_t)BATCH * D * D];   // 16 MB: K = exp(symmetrized w0)
__device__ float g_qu[BATCH * D];              // q_128 = exp(-u_64)  (row potential)
__device__ float g_qv[BATCH * D];              // q_127 = exp(-v_64)  (col potential)

// ---------------------------------------------------------------------------
// Prep: K[b][i][j] = exp(0.5*(xp[b,1+i,1+j]+xp[b,1+j,1+i])), diag = exp(xu[b,1+i])
// Tiled 32x32 transpose for coalesced access to both triangles.
// ---------------------------------------------------------------------------
__global__ void prep_kernel(const float* __restrict__ xp,
                            const float* __restrict__ xu) {
    __shared__ float s[32][33];
    const int b  = blockIdx.z;
    const int it = blockIdx.y;
    const int jt = blockIdx.x;
    const int tx = threadIdx.x;      // 0..31
    const int ty = threadIdx.y;      // 0..7
    const float* xpb = xp + (size_t)b * LDIM * LDIM;

    // Load the transposed-source tile: rows from j-block, cols from i-block
    #pragma unroll
    for (int k = 0; k < 32; k += 8) {
        int j = jt * 32 + ty + k;
        int i = it * 32 + tx;
        s[ty + k][tx] = xpb[(size_t)(1 + j) * LDIM + (1 + i)];
    }
    __syncthreads();

    float* Kb = g_K + (size_t)b * D * D;
    #pragma unroll
    for (int k = 0; k < 32; k += 8) {
        int i = it * 32 + ty + k;
        int j = jt * 32 + tx;
        float a = xpb[(size_t)(1 + i) * LDIM + (1 + j)];
        float t = s[tx][ty + k];               // xp[b, 1+j, 1+i]
        float v = 0.5f * (a + t);
        if (i == j) v = xu[b * LDIM + 1 + i];
        Kb[(size_t)i * D + j] = expf(v);
    }
}

// ---------------------------------------------------------------------------
// Persistent iteration kernel: one 8-CTA cluster per batch, 256 thr/CTA.
// Each CTA owns 64 rows of K, register-resident (8 rows x 16 cols per lane).
// Per iteration: q_new[r] = 1 / dot(K[r,:], q); broadcast via DSMEM stores;
// cluster barrier between iterations.
// ---------------------------------------------------------------------------
__global__ void __launch_bounds__(256, 1) iter_kernel() {
    __shared__ float qbuf[2][D];   // ping-pong q vectors (local copy per CTA)

    unsigned rank;
    asm("mov.u32 %0, %%cluster_ctarank;" : "=r"(rank));
    const int batch = blockIdx.x >> 3;
    const int tid   = threadIdx.x;
    const int wid   = tid >> 5;
    const int lane  = tid & 31;

    // ---- Load K fragment into registers: rows [rank*64 + wid*8, +8), cols [lane*16, +16)
    const int row0 = (int)rank * 64 + wid * 8;
    const float4* Kb = (const float4*)(g_K + (size_t)batch * D * D);
    float4 kf[8][4];
    #pragma unroll
    for (int r = 0; r < 8; r++) {
        const float4* rowp = Kb + (size_t)(row0 + r) * (D / 4) + lane * 4;
        #pragma unroll
        for (int c = 0; c < 4; c++) kf[r][c] = rowp[c];
    }

    // ---- q_0 = 1
    qbuf[0][tid]       = 1.0f;
    qbuf[0][tid + 256] = 1.0f;

    const uint32_t q0_base = (uint32_t)__cvta_generic_to_shared(&qbuf[0][0]);
    const uint32_t q1_base = (uint32_t)__cvta_generic_to_shared(&qbuf[1][0]);

    asm volatile("barrier.cluster.arrive.aligned;\n\t"
                 "barrier.cluster.wait.aligned;" ::: "memory");

    #pragma unroll 1
    for (int it = 0; it < NITER; it++) {
        const float* qc = qbuf[it & 1];
        // q fragment for this lane's 16 columns
        float4 qv0 = *(const float4*)&qc[lane * 16 + 0];
        float4 qv1 = *(const float4*)&qc[lane * 16 + 4];
        float4 qv2 = *(const float4*)&qc[lane * 16 + 8];
        float4 qv3 = *(const float4*)&qc[lane * 16 + 12];

        float acc[8];
        #pragma unroll
        for (int r = 0; r < 8; r++) {
            float s0 = kf[r][0].x * qv0.x;
            s0 = fmaf(kf[r][0].y, qv0.y, s0);
            s0 = fmaf(kf[r][0].z, qv0.z, s0);
            s0 = fmaf(kf[r][0].w, qv0.w, s0);
            float s1 = kf[r][1].x * qv1.x;
            s1 = fmaf(kf[r][1].y, qv1.y, s1);
            s1 = fmaf(kf[r][1].z, qv1.z, s1);
            s1 = fmaf(kf[r][1].w, qv1.w, s1);
            float s2 = kf[r][2].x * qv2.x;
            s2 = fmaf(kf[r][2].y, qv2.y, s2);
            s2 = fmaf(kf[r][2].z, qv2.z, s2);
            s2 = fmaf(kf[r][2].w, qv2.w, s2);
            float s3 = kf[r][3].x * qv3.x;
            s3 = fmaf(kf[r][3].y, qv3.y, s3);
            s3 = fmaf(kf[r][3].z, qv3.z, s3);
            s3 = fmaf(kf[r][3].w, qv3.w, s3);
            acc[r] = (s0 + s1) + (s2 + s3);
        }

        // Warp butterfly reduction (all lanes end with the full row sums)
        #pragma unroll
        for (int off = 16; off > 0; off >>= 1) {
            #pragma unroll
            for (int r = 0; r < 8; r++)
                acc[r] += __shfl_xor_sync(0xffffffffu, acc[r], off);
        }

        // Lanes 0..7 publish q_new for rows row0+lane to all 8 cluster CTAs
        if (lane < 8) {
            float s = (lane == 0) ? acc[0] :
                      (lane == 1) ? acc[1] :
                      (lane == 2) ? acc[2] :
                      (lane == 3) ? acc[3] :
                      (lane == 4) ? acc[4] :
                      (lane == 5) ? acc[5] :
                      (lane == 6) ? acc[6] : acc[7];
            float inv = __fdividef(1.0f, s);
            int row = row0 + lane;
            // write into the *other* buffer: it even -> buf1, it odd -> buf0
            uint32_t dst = ((it & 1) ? q0_base : q1_base) + (uint32_t)row * 4u;
            #pragma unroll
            for (int p = 0; p < 8; p++) {
                uint32_t remote;
                asm volatile("mapa.shared::cluster.u32 %0, %1, %2;"
                             : "=r"(remote) : "r"(dst), "r"(p));
                asm volatile("st.shared::cluster.f32 [%0], %1;"
                             :: "r"(remote), "f"(inv) : "memory");
            }
        }

        asm volatile("barrier.cluster.arrive.aligned;\n\t"
                     "barrier.cluster.wait.aligned;" ::: "memory");
    }

    // qbuf[0] = q_128 = exp(-u_64); qbuf[1] = q_127 = exp(-v_64)
    if (tid < 64) {
        int row = (int)rank * 64 + tid;
        g_qu[batch * D + row] = qbuf[0][row];
        g_qv[batch * D + row] = qbuf[1][row];
    }
}

// ---------------------------------------------------------------------------
// Writeback: xp output then xu output
// ---------------------------------------------------------------------------
__global__ void out_xp_kernel(const float* __restrict__ xp,
                              float* __restrict__ out) {
    int idx = blockIdx.x * blockDim.x + threadIdx.x;
    const int total = BATCH * LDIM * LDIM;
    if (idx >= total) return;
    int b   = idx / (LDIM * LDIM);
    int rem = idx - b * (LDIM * LDIM);
    int i = rem / LDIM;
    int j = rem - i * LDIM;
    float v;
    if (i == 0 && j == 0)       v = expf(xp[idx]);
    else if (i == 0 || j == 0)  v = xp[idx];
    else if (i == j)            v = 0.0f;                  // offdiag has zero diagonal
    else {
        v = g_K[((size_t)b * D + (i - 1)) * D + (j - 1)]
            * g_qu[b * D + i - 1] * g_qv[b * D + j - 1];
    }
    out[idx] = v;
}

__global__ void out_xu_kernel(const float* __restrict__ xu,
                              float* __restrict__ out) {
    int idx = blockIdx.x * blockDim.x + threadIdx.x;
    const int total = BATCH * LDIM;
    if (idx >= total) return;
    int b = idx / LDIM;
    int i = idx - b * LDIM;
    float v;
    if (i == 0) v = expf(xu[idx]);
    else {
        int d = i - 1;
        v = g_K[((size_t)b * D + d) * D + d]
            * g_qu[b * D + d] * g_qv[b * D + d];
    }
    out[idx] = v;
}

// ---------------------------------------------------------------------------
extern "C" void kernel_launch(void* const* d_in, const int* in_sizes, int n_in,
                              void* d_out, int out_size) {
    // Defensive input identification by size (x_paired is the big one)
    const float* xp;
    const float* xu;
    if (in_sizes[0] >= in_sizes[1]) { xp = (const float*)d_in[0]; xu = (const float*)d_in[1]; }
    else                            { xp = (const float*)d_in[1]; xu = (const float*)d_in[0]; }
    float* out = (float*)d_out;

    // 1) Build K = exp(symmetrized w0)
    dim3 pb(32, 8), pg(D / 32, D / 32, BATCH);
    prep_kernel<<<pg, pb>>>(xp, xu);

    // 2) 128 Sinkhorn half-steps, one 8-CTA cluster per batch
    cudaLaunchConfig_t cfg = {};
    cfg.gridDim  = dim3(BATCH * 8);
    cfg.blockDim = dim3(256);
    cfg.dynamicSmemBytes = 0;
    cfg.stream = 0;
    cudaLaunchAttribute attrs[1];
    attrs[0].id = cudaLaunchAttributeClusterDimension;
    attrs[0].val.clusterDim.x = 8;
    attrs[0].val.clusterDim.y = 1;
    attrs[0].val.clusterDim.z = 1;
    cfg.attrs = attrs;
    cfg.numAttrs = 1;
    cudaLaunchKernelEx(&cfg, iter_kernel);

    // 3) Writeback
    const int t1 = BATCH * LDIM * LDIM;
    out_xp_kernel<<<(t1 + 255) / 256, 256>>>(xp, out);
    const int t2 = BATCH * LDIM;
    out_xu_kernel<<<(t2 + 255) / 256, 256>>>(xu, out + (size_t)t1);
}